// round 1
// baseline (speedup 1.0000x reference)
#include <cuda_runtime.h>

#define BATCH 2
#define CH 256
#define NTOK 4096
#define NHEAD 8
#define HDIM 32
#define SCALE 0.17677669529663687f   // 1/sqrt(32)

// ---------------- scratch (no allocations allowed) ----------------
__device__ float g_tn[BATCH * CH * NTOK];              // layernorm out, [b][c][n]
__device__ float g_q [BATCH * NHEAD * NTOK * HDIM];    // [b][h][n][d]
__device__ float g_k [BATCH * NHEAD * NTOK * HDIM];
__device__ float g_v [BATCH * NHEAD * NTOK * HDIM];
__device__ float g_ao[BATCH * NTOK * CH];              // attn out, [b][n][c]

// ---------------- kernel 1: LayerNorm (channel dim) ----------------
// x is [b][c][n]; thread per token n -> all gmem accesses coalesced along n.
__global__ void ln_kernel(const float* __restrict__ x,
                          const float* __restrict__ gamma,
                          const float* __restrict__ beta) {
    int n = blockIdx.x * blockDim.x + threadIdx.x;
    int b = blockIdx.y;
    const float* xb = x + b * CH * NTOK + n;
    float s = 0.f, ss = 0.f;
#pragma unroll 8
    for (int c = 0; c < CH; c++) {
        float v = xb[c * NTOK];
        s += v; ss += v * v;
    }
    float mu  = s * (1.0f / CH);
    float var = ss * (1.0f / CH) - mu * mu;
    float r   = rsqrtf(var + 1e-5f);
    float* tb = g_tn + b * CH * NTOK + n;
#pragma unroll 8
    for (int c = 0; c < CH; c++) {
        float v = xb[c * NTOK];
        tb[c * NTOK] = (v - mu) * r * __ldg(&gamma[c]) + __ldg(&beta[c]);
    }
}

// ---------------- kernel 2: QKV GEMM ----------------
// qkv[m][o] = sum_c tn[c][m] * w[o][c]    (m = token within batch, o in [0,768))
// Tile: 64(m) x 64(o) x 16(k), 128 threads, 4x8 register tile per thread.
__global__ void __launch_bounds__(128) qkv_gemm_kernel(const float* __restrict__ w) {
    const int b  = blockIdx.z;
    const int m0 = blockIdx.x * 64;
    const int o0 = blockIdx.y * 64;
    const int tid = threadIdx.x;
    const int tx = tid & 15;   // m group (16 groups * 4 rows)
    const int ty = tid >> 4;   // o group (8 groups * 8 cols)

    __shared__ float As[16 * 68];
    __shared__ float Bs[16 * 68];

    float acc[4][8];
#pragma unroll
    for (int i = 0; i < 4; i++)
#pragma unroll
        for (int j = 0; j < 8; j++) acc[i][j] = 0.f;

    const float* aBase = g_tn + b * CH * NTOK;

    for (int kt = 0; kt < CH; kt += 16) {
        // load A tile: As[k][m], gmem already k-major -> coalesced float4 along m
#pragma unroll
        for (int i = 0; i < 2; i++) {
            int t4 = tid * 2 + i;
            int k  = t4 >> 4;
            int mq = (t4 & 15) * 4;
            float4 v = *(const float4*)&aBase[(kt + k) * NTOK + m0 + mq];
            *(float4*)&As[k * 68 + mq] = v;
        }
        // load B tile: Bs[k][o] from w[o][k] (transpose in smem)
#pragma unroll
        for (int i = 0; i < 2; i++) {
            int t4 = tid * 2 + i;
            int o  = t4 >> 2;
            int kq = (t4 & 3) * 4;
            float4 v = *(const float4*)&w[(o0 + o) * CH + kt + kq];
            Bs[(kq + 0) * 68 + o] = v.x;
            Bs[(kq + 1) * 68 + o] = v.y;
            Bs[(kq + 2) * 68 + o] = v.z;
            Bs[(kq + 3) * 68 + o] = v.w;
        }
        __syncthreads();
#pragma unroll
        for (int k = 0; k < 16; k++) {
            float4 a  = *(float4*)&As[k * 68 + tx * 4];
            float4 b0 = *(float4*)&Bs[k * 68 + ty * 8];
            float4 b1 = *(float4*)&Bs[k * 68 + ty * 8 + 4];
            float av[4] = {a.x, a.y, a.z, a.w};
            float bv[8] = {b0.x, b0.y, b0.z, b0.w, b1.x, b1.y, b1.z, b1.w};
#pragma unroll
            for (int i = 0; i < 4; i++)
#pragma unroll
                for (int j = 0; j < 8; j++) acc[i][j] += av[i] * bv[j];
        }
        __syncthreads();
    }

    // scatter epilogue into q/k/v [b][h][n][d]
    const int which = o0 >> 8;                 // 64 | 256 -> constant per block
    float* outp = (which == 0) ? g_q : (which == 1) ? g_k : g_v;
#pragma unroll
    for (int j = 0; j < 8; j++) {
        int o  = o0 + ty * 8 + j;
        int h  = (o >> 5) & 7;
        int dd = o & 31;
#pragma unroll
        for (int i = 0; i < 4; i++) {
            int m = m0 + tx * 4 + i;
            outp[((b * NHEAD + h) * NTOK + m) * HDIM + dd] = acc[i][j];
        }
    }
}

// ---------------- kernel 3: flash attention ----------------
// One CTA = (b, h, 64-query block). BM=BN=64, d=32, 128 threads.
// Thread layout: rg = tid>>3 (16 row groups * 4 rows), cg = tid&7 (8 col groups).
// Smem xor-swizzled at float4 granularity for conflict-free Q/K/P reads.
__global__ void __launch_bounds__(128) flash_kernel() {
    const int b  = blockIdx.z;
    const int h  = blockIdx.y;
    const int n0 = blockIdx.x * 64;
    const int tid = threadIdx.x;
    const int rg = tid >> 3;
    const int cg = tid & 7;

    __shared__ float Qs[64 * 32];
    __shared__ float Ks[64 * 32];
    __shared__ float Vs[64 * 32];
    __shared__ float Ps[64 * 64];

    const float* qsrc = g_q + (((b * NHEAD + h) * NTOK) + n0) * HDIM;
    const float* ksrc = g_k + ((b * NHEAD + h) * NTOK) * HDIM;
    const float* vsrc = g_v + ((b * NHEAD + h) * NTOK) * HDIM;

    // load Q once, fold in softmax scale; swizzle chunk: k4 ^ (row>>2 & 7)
#pragma unroll
    for (int ii = 0; ii < 4; ii++) {
        int t4  = tid + 128 * ii;
        int row = t4 >> 3, k4 = t4 & 7;
        float4 v = *(const float4*)&qsrc[row * HDIM + k4 * 4];
        v.x *= SCALE; v.y *= SCALE; v.z *= SCALE; v.w *= SCALE;
        *(float4*)&Qs[row * 32 + ((k4 ^ ((row >> 2) & 7)) << 2)] = v;
    }

    float m_[4], l_[4], o_[4][4];
#pragma unroll
    for (int i = 0; i < 4; i++) {
        m_[i] = -1e30f; l_[i] = 0.f;
#pragma unroll
        for (int c = 0; c < 4; c++) o_[i][c] = 0.f;
    }

    for (int j0 = 0; j0 < NTOK; j0 += 64) {
        __syncthreads();   // prev PV done -> safe to overwrite Ks/Vs/Ps
        // load K (swizzle k4 ^ (row&7)) and V (plain)
#pragma unroll
        for (int ii = 0; ii < 4; ii++) {
            int t4  = tid + 128 * ii;
            int row = t4 >> 3, k4 = t4 & 7;
            float4 kv = *(const float4*)&ksrc[(j0 + row) * HDIM + k4 * 4];
            *(float4*)&Ks[row * 32 + ((k4 ^ (row & 7)) << 2)] = kv;
            float4 vv = *(const float4*)&vsrc[(j0 + row) * HDIM + k4 * 4];
            *(float4*)&Vs[row * 32 + k4 * 4] = vv;
        }
        __syncthreads();

        // S = Q K^T (scale already in Q)
        float acc[4][8];
#pragma unroll
        for (int i = 0; i < 4; i++)
#pragma unroll
            for (int j = 0; j < 8; j++) acc[i][j] = 0.f;
#pragma unroll
        for (int k4 = 0; k4 < 8; k4++) {
            float4 q[4], kk[8];
#pragma unroll
            for (int i = 0; i < 4; i++)
                q[i] = *(const float4*)&Qs[(rg * 4 + i) * 32 + ((k4 ^ (rg & 7)) << 2)];
#pragma unroll
            for (int j = 0; j < 8; j++)
                kk[j] = *(const float4*)&Ks[(j * 8 + cg) * 32 + ((k4 ^ cg) << 2)];
#pragma unroll
            for (int i = 0; i < 4; i++)
#pragma unroll
                for (int j = 0; j < 8; j++) {
                    acc[i][j] += q[i].x * kk[j].x;
                    acc[i][j] += q[i].y * kk[j].y;
                    acc[i][j] += q[i].z * kk[j].z;
                    acc[i][j] += q[i].w * kk[j].w;
                }
        }

        // online softmax (rows owned by 8 consecutive lanes -> shfl reduce)
#pragma unroll
        for (int i = 0; i < 4; i++) {
            float mx = acc[i][0];
#pragma unroll
            for (int j = 1; j < 8; j++) mx = fmaxf(mx, acc[i][j]);
            mx = fmaxf(mx, __shfl_xor_sync(0xffffffffu, mx, 1));
            mx = fmaxf(mx, __shfl_xor_sync(0xffffffffu, mx, 2));
            mx = fmaxf(mx, __shfl_xor_sync(0xffffffffu, mx, 4));
            float mnew  = fmaxf(m_[i], mx);
            float alpha = __expf(m_[i] - mnew);
            float sum = 0.f;
#pragma unroll
            for (int j = 0; j < 8; j++) {
                float p = __expf(acc[i][j] - mnew);
                acc[i][j] = p;
                sum += p;
            }
            sum += __shfl_xor_sync(0xffffffffu, sum, 1);
            sum += __shfl_xor_sync(0xffffffffu, sum, 2);
            sum += __shfl_xor_sync(0xffffffffu, sum, 4);
            l_[i] = l_[i] * alpha + sum;
            m_[i] = mnew;
            o_[i][0] *= alpha; o_[i][1] *= alpha; o_[i][2] *= alpha; o_[i][3] *= alpha;
        }

        // write P (swizzle chunk: c4 ^ (row>>2))
#pragma unroll
        for (int i = 0; i < 4; i++) {
            int row = rg * 4 + i;
#pragma unroll
            for (int j = 0; j < 8; j++) {
                int col = j * 8 + cg;
                Ps[row * 64 + ((((col >> 2) ^ rg) & 15) << 2) + (col & 3)] = acc[i][j];
            }
        }
        __syncthreads();

        // O += P V
#pragma unroll
        for (int j4 = 0; j4 < 16; j4++) {
            float4 p[4];
#pragma unroll
            for (int i = 0; i < 4; i++)
                p[i] = *(const float4*)&Ps[(rg * 4 + i) * 64 + ((j4 ^ rg) << 2)];
#pragma unroll
            for (int jj = 0; jj < 4; jj++) {
                float4 v = *(const float4*)&Vs[(j4 * 4 + jj) * 32 + cg * 4];
#pragma unroll
                for (int i = 0; i < 4; i++) {
                    float pv = ((const float*)&p[i])[jj];
                    o_[i][0] += pv * v.x;
                    o_[i][1] += pv * v.y;
                    o_[i][2] += pv * v.z;
                    o_[i][3] += pv * v.w;
                }
            }
        }
    }

    // normalize + write attn out [b][n][c] (c = h*32 + cg*4 + cc)
#pragma unroll
    for (int i = 0; i < 4; i++) {
        float inv = 1.0f / l_[i];
        int n = n0 + rg * 4 + i;
        float4 r;
        r.x = o_[i][0] * inv; r.y = o_[i][1] * inv;
        r.z = o_[i][2] * inv; r.w = o_[i][3] * inv;
        *(float4*)&g_ao[(b * NTOK + n) * CH + h * HDIM + cg * 4] = r;
    }
}

// ---------------- kernel 4: proj GEMM + bias + residual + token2patch ----------------
// out[b][o][n] = x[b][o][n] + b_proj[o] + sum_c ao[b][n][c] * w_proj[o][c]
__global__ void __launch_bounds__(128) proj_kernel(const float* __restrict__ x,
                                                   const float* __restrict__ w,
                                                   const float* __restrict__ bias,
                                                   float* __restrict__ out) {
    const int b  = blockIdx.z;
    const int m0 = blockIdx.x * 64;
    const int o0 = blockIdx.y * 64;
    const int tid = threadIdx.x;
    const int tx = tid & 15;
    const int ty = tid >> 4;

    __shared__ float As[16 * 68];
    __shared__ float Bs[16 * 68];

    float acc[4][8];
#pragma unroll
    for (int i = 0; i < 4; i++)
#pragma unroll
        for (int j = 0; j < 8; j++) acc[i][j] = 0.f;

    const float* aBase = g_ao + b * NTOK * CH;

    for (int kt = 0; kt < CH; kt += 16) {
#pragma unroll
        for (int i = 0; i < 2; i++) {        // A: [m][k] row-major -> As[k][m]
            int t4 = tid * 2 + i;
            int m  = t4 >> 2;
            int kq = (t4 & 3) * 4;
            float4 v = *(const float4*)&aBase[(m0 + m) * CH + kt + kq];
            As[(kq + 0) * 68 + m] = v.x;
            As[(kq + 1) * 68 + m] = v.y;
            As[(kq + 2) * 68 + m] = v.z;
            As[(kq + 3) * 68 + m] = v.w;
        }
#pragma unroll
        for (int i = 0; i < 2; i++) {        // B: w[o][k] -> Bs[k][o]
            int t4 = tid * 2 + i;
            int o  = t4 >> 2;
            int kq = (t4 & 3) * 4;
            float4 v = *(const float4*)&w[(o0 + o) * CH + kt + kq];
            Bs[(kq + 0) * 68 + o] = v.x;
            Bs[(kq + 1) * 68 + o] = v.y;
            Bs[(kq + 2) * 68 + o] = v.z;
            Bs[(kq + 3) * 68 + o] = v.w;
        }
        __syncthreads();
#pragma unroll
        for (int k = 0; k < 16; k++) {
            float4 a  = *(float4*)&As[k * 68 + tx * 4];
            float4 b0 = *(float4*)&Bs[k * 68 + ty * 8];
            float4 b1 = *(float4*)&Bs[k * 68 + ty * 8 + 4];
            float av[4] = {a.x, a.y, a.z, a.w};
            float bv[8] = {b0.x, b0.y, b0.z, b0.w, b1.x, b1.y, b1.z, b1.w};
#pragma unroll
            for (int i = 0; i < 4; i++)
#pragma unroll
                for (int j = 0; j < 8; j++) acc[i][j] += av[i] * bv[j];
        }
        __syncthreads();
    }

    // fused epilogue: bias + residual, float4 stores coalesced along n
#pragma unroll
    for (int j = 0; j < 8; j++) {
        int o = o0 + ty * 8 + j;
        float bp = __ldg(&bias[o]);
        int base = b * CH * NTOK + o * NTOK + m0 + tx * 4;
        float4 xv = *(const float4*)&x[base];
        float4 r;
        r.x = acc[0][j] + xv.x + bp;
        r.y = acc[1][j] + xv.y + bp;
        r.z = acc[2][j] + xv.z + bp;
        r.w = acc[3][j] + xv.w + bp;
        *(float4*)&out[base] = r;
    }
}

// ---------------- launch ----------------
extern "C" void kernel_launch(void* const* d_in, const int* in_sizes, int n_in,
                              void* d_out, int out_size) {
    const float* x      = (const float*)d_in[0];
    const float* gamma  = (const float*)d_in[1];
    const float* beta   = (const float*)d_in[2];
    const float* w_qkv  = (const float*)d_in[3];
    const float* w_proj = (const float*)d_in[4];
    const float* b_proj = (const float*)d_in[5];
    float* out = (float*)d_out;

    ln_kernel<<<dim3(NTOK / 256, BATCH), 256>>>(x, gamma, beta);
    qkv_gemm_kernel<<<dim3(NTOK / 64, 12, BATCH), 128>>>(w_qkv);
    flash_kernel<<<dim3(NTOK / 64, NHEAD, BATCH), 128>>>();
    proj_kernel<<<dim3(NTOK / 64, CH / 64, BATCH), 128>>>(x, w_proj, b_proj, out);
}

// round 3
// speedup vs baseline: 3.4553x; 3.4553x over previous
#include <cuda_runtime.h>
#include <cuda_bf16.h>
#include <cstdint>

#define BATCH 2
#define CH 256
#define NTOK 4096
#define NHEAD 8
#define HDIM 32
#define SCALE 0.17677669529663687f   // 1/sqrt(32)

// ---------------- scratch (no allocations allowed) ----------------
__device__ float g_tn[BATCH * CH * NTOK];                       // layernorm out, [b][c][n]
__device__ __nv_bfloat16 g_q [BATCH * NHEAD * NTOK * HDIM];     // [b][h][n][d], pre-scaled
__device__ __nv_bfloat16 g_k [BATCH * NHEAD * NTOK * HDIM];     // [b][h][n][d]
__device__ __nv_bfloat16 g_vt[BATCH * NHEAD * HDIM * NTOK];     // [b][h][d][n]  (V transposed)
__device__ float g_ao[BATCH * NTOK * CH];                       // attn out, [b][n][c]

// ---------------- mma helpers ----------------
__device__ __forceinline__ void ldsm_x4(uint32_t* r, uint32_t saddr) {
    asm volatile("ldmatrix.sync.aligned.m8n8.x4.shared.b16 {%0,%1,%2,%3}, [%4];"
                 : "=r"(r[0]), "=r"(r[1]), "=r"(r[2]), "=r"(r[3]) : "r"(saddr));
}

__device__ __forceinline__ void mma16816(float* c, const uint32_t* a, uint32_t b0, uint32_t b1) {
    asm volatile("mma.sync.aligned.m16n8k16.row.col.f32.bf16.bf16.f32 "
                 "{%0,%1,%2,%3}, {%4,%5,%6,%7}, {%8,%9}, {%0,%1,%2,%3};"
                 : "+f"(c[0]), "+f"(c[1]), "+f"(c[2]), "+f"(c[3])
                 : "r"(a[0]), "r"(a[1]), "r"(a[2]), "r"(a[3]), "r"(b0), "r"(b1));
}

__device__ __forceinline__ uint32_t pack_bf16x2(float lo, float hi) {
    uint32_t r;
    asm("cvt.rn.bf16x2.f32 %0, %1, %2;" : "=r"(r) : "f"(hi), "f"(lo));
    return r;
}

// ---------------- kernel 1: LayerNorm (channel dim) ----------------
__global__ void ln_kernel(const float* __restrict__ x,
                          const float* __restrict__ gamma,
                          const float* __restrict__ beta) {
    int n = blockIdx.x * blockDim.x + threadIdx.x;
    int b = blockIdx.y;
    const float* xb = x + b * CH * NTOK + n;
    float s = 0.f, ss = 0.f;
#pragma unroll 8
    for (int c = 0; c < CH; c++) {
        float v = xb[c * NTOK];
        s += v; ss += v * v;
    }
    float mu  = s * (1.0f / CH);
    float var = ss * (1.0f / CH) - mu * mu;
    float r   = rsqrtf(var + 1e-5f);
    float* tb = g_tn + b * CH * NTOK + n;
#pragma unroll 8
    for (int c = 0; c < CH; c++) {
        float v = xb[c * NTOK];
        tb[c * NTOK] = (v - mu) * r * __ldg(&gamma[c]) + __ldg(&beta[c]);
    }
}

// ---------------- kernel 2: QKV GEMM (fp32 compute, bf16 output) ----------------
__global__ void __launch_bounds__(128) qkv_gemm_kernel(const float* __restrict__ w) {
    const int b  = blockIdx.z;
    const int m0 = blockIdx.x * 64;
    const int o0 = blockIdx.y * 64;
    const int tid = threadIdx.x;
    const int tx = tid & 15;
    const int ty = tid >> 4;

    __shared__ float As[16 * 68];
    __shared__ float Bs[16 * 68];

    float acc[4][8];
#pragma unroll
    for (int i = 0; i < 4; i++) {
#pragma unroll
        for (int j = 0; j < 8; j++) { acc[i][j] = 0.f; }
    }

    const float* aBase = g_tn + b * CH * NTOK;

    for (int kt = 0; kt < CH; kt += 16) {
#pragma unroll
        for (int i = 0; i < 2; i++) {
            int t4 = tid * 2 + i;
            int k  = t4 >> 4;
            int mq = (t4 & 15) * 4;
            float4 v = *(const float4*)&aBase[(kt + k) * NTOK + m0 + mq];
            *(float4*)&As[k * 68 + mq] = v;
        }
#pragma unroll
        for (int i = 0; i < 2; i++) {
            int t4 = tid * 2 + i;
            int o  = t4 >> 2;
            int kq = (t4 & 3) * 4;
            float4 v = *(const float4*)&w[(o0 + o) * CH + kt + kq];
            Bs[(kq + 0) * 68 + o] = v.x;
            Bs[(kq + 1) * 68 + o] = v.y;
            Bs[(kq + 2) * 68 + o] = v.z;
            Bs[(kq + 3) * 68 + o] = v.w;
        }
        __syncthreads();
#pragma unroll
        for (int k = 0; k < 16; k++) {
            float4 a  = *(float4*)&As[k * 68 + tx * 4];
            float4 b0 = *(float4*)&Bs[k * 68 + ty * 8];
            float4 b1 = *(float4*)&Bs[k * 68 + ty * 8 + 4];
            float av[4] = {a.x, a.y, a.z, a.w};
            float bv[8] = {b0.x, b0.y, b0.z, b0.w, b1.x, b1.y, b1.z, b1.w};
#pragma unroll
            for (int i = 0; i < 4; i++) {
#pragma unroll
                for (int j = 0; j < 8; j++) { acc[i][j] += av[i] * bv[j]; }
            }
        }
        __syncthreads();
    }

    const int which = o0 >> 8;   // 0:q 1:k 2:v  (constant per block)
    if (which < 2) {
        const float sc = (which == 0) ? SCALE : 1.0f;
        __nv_bfloat16* outp = (which == 0) ? g_q : g_k;
        const int o  = o0 + ty * 8;
        const int h  = (o >> 5) & 7;
        const int dd = o & 31;
#pragma unroll
        for (int i = 0; i < 4; i++) {
            int m = m0 + tx * 4 + i;
            __nv_bfloat16 tmp[8];
#pragma unroll
            for (int j = 0; j < 8; j++) { tmp[j] = __float2bfloat16_rn(acc[i][j] * sc); }
            *(uint4*)&outp[((size_t)(b * NHEAD + h) * NTOK + m) * HDIM + dd] = *(uint4*)tmp;
        }
    } else {
#pragma unroll
        for (int j = 0; j < 8; j++) {
            int o  = o0 + ty * 8 + j;
            int h  = (o >> 5) & 7;
            int dd = o & 31;
            __nv_bfloat16 tmp[4];
#pragma unroll
            for (int i = 0; i < 4; i++) { tmp[i] = __float2bfloat16_rn(acc[i][j]); }
            *(uint2*)&g_vt[((size_t)(b * NHEAD + h) * HDIM + dd) * NTOK + m0 + tx * 4] = *(uint2*)tmp;
        }
    }
}

// ---------------- kernel 3: flash attention, bf16 mma.sync ----------------
// CTA: (b, h, 128-row Q block). 4 warps x 32 rows each. BN=64 per KV iter.
// Smem pitches 40 / 72 bf16 (5 / 9 x 16B chunks, coprime to 8) -> ldmatrix conflict-free.
__global__ void __launch_bounds__(128) flash_mma_kernel() {
    const int b  = blockIdx.z;
    const int h  = blockIdx.y;
    const int n0 = blockIdx.x * 128;
    const int tid  = threadIdx.x;
    const int warp = tid >> 5;
    const int lane = tid & 31;

    __shared__ __nv_bfloat16 Qs[128 * 40];
    __shared__ __nv_bfloat16 Ks[64 * 40];
    __shared__ __nv_bfloat16 Vts[32 * 72];

    const __nv_bfloat16* qsrc  = g_q  + ((size_t)(b * NHEAD + h) * NTOK + n0) * HDIM;
    const __nv_bfloat16* ksrc  = g_k  + (size_t)(b * NHEAD + h) * NTOK * HDIM;
    const __nv_bfloat16* vtsrc = g_vt + (size_t)(b * NHEAD + h) * HDIM * NTOK;

    // load Q (128x32 bf16), row pitch 40
#pragma unroll
    for (int ii = 0; ii < 4; ii++) {
        int idx = tid + 128 * ii;
        int row = idx >> 2;
        int cc  = idx & 3;
        *(uint4*)&Qs[row * 40 + cc * 8] = *(const uint4*)&qsrc[row * 32 + cc * 8];
    }
    __syncthreads();

    // preload Q A-fragments (softmax scale already folded in)
    uint32_t aq[2][2][4];
    const int mbase = warp * 32;
#pragma unroll
    for (int mt = 0; mt < 2; mt++) {
        uint32_t base = (uint32_t)__cvta_generic_to_shared(
            &Qs[(mbase + mt * 16 + (lane & 15)) * 40 + (lane >> 4) * 8]);
        ldsm_x4(aq[mt][0], base);        // k 0..15
        ldsm_x4(aq[mt][1], base + 32);   // k 16..31 (+16 elems = +32 bytes)
    }

    float m_[2][2], l_[2][2], o_[2][4][4];
#pragma unroll
    for (int mt = 0; mt < 2; mt++) {
        m_[mt][0] = -1e30f; m_[mt][1] = -1e30f;
        l_[mt][0] = 0.f;    l_[mt][1] = 0.f;
#pragma unroll
        for (int dt = 0; dt < 4; dt++) {
#pragma unroll
            for (int c = 0; c < 4; c++) { o_[mt][dt][c] = 0.f; }
        }
    }

    for (int j0 = 0; j0 < NTOK; j0 += 64) {
        __syncthreads();   // prev iter's ldmatrix reads done -> safe to overwrite
        // load K (64x32, pitch 40) and Vt (32x64, pitch 72)
#pragma unroll
        for (int ii = 0; ii < 2; ii++) {
            int idx = tid + 128 * ii;
            int row = idx >> 2;
            int cc  = idx & 3;
            *(uint4*)&Ks[row * 40 + cc * 8] = *(const uint4*)&ksrc[(j0 + row) * 32 + cc * 8];
        }
#pragma unroll
        for (int ii = 0; ii < 2; ii++) {
            int idx = tid + 128 * ii;
            int row = idx >> 3;
            int cc  = idx & 7;
            *(uint4*)&Vts[row * 72 + cc * 8] = *(const uint4*)&vtsrc[(size_t)row * NTOK + j0 + cc * 8];
        }
        __syncthreads();

        // S = Q K^T
        float s[2][8][4];
#pragma unroll
        for (int mt = 0; mt < 2; mt++) {
#pragma unroll
            for (int nt = 0; nt < 8; nt++) {
#pragma unroll
                for (int c = 0; c < 4; c++) { s[mt][nt][c] = 0.f; }
            }
        }

#pragma unroll
        for (int nt = 0; nt < 8; nt++) {
            uint32_t kb[4];
            uint32_t kaddr = (uint32_t)__cvta_generic_to_shared(
                &Ks[(nt * 8 + (lane & 7)) * 40 + (lane >> 3) * 8]);
            ldsm_x4(kb, kaddr);
#pragma unroll
            for (int mt = 0; mt < 2; mt++) {
                mma16816(s[mt][nt], aq[mt][0], kb[0], kb[1]);
                mma16816(s[mt][nt], aq[mt][1], kb[2], kb[3]);
            }
        }

        // online softmax (rows r = lane>>2 and r+8 within each m16 tile)
#pragma unroll
        for (int mt = 0; mt < 2; mt++) {
            float mx0 = -1e30f, mx1 = -1e30f;
#pragma unroll
            for (int nt = 0; nt < 8; nt++) {
                mx0 = fmaxf(mx0, fmaxf(s[mt][nt][0], s[mt][nt][1]));
                mx1 = fmaxf(mx1, fmaxf(s[mt][nt][2], s[mt][nt][3]));
            }
            mx0 = fmaxf(mx0, __shfl_xor_sync(0xffffffffu, mx0, 1));
            mx0 = fmaxf(mx0, __shfl_xor_sync(0xffffffffu, mx0, 2));
            mx1 = fmaxf(mx1, __shfl_xor_sync(0xffffffffu, mx1, 1));
            mx1 = fmaxf(mx1, __shfl_xor_sync(0xffffffffu, mx1, 2));
            float mn0 = fmaxf(m_[mt][0], mx0);
            float mn1 = fmaxf(m_[mt][1], mx1);
            float a0 = __expf(m_[mt][0] - mn0);
            float a1 = __expf(m_[mt][1] - mn1);
            float sum0 = 0.f, sum1 = 0.f;
#pragma unroll
            for (int nt = 0; nt < 8; nt++) {
                s[mt][nt][0] = __expf(s[mt][nt][0] - mn0);
                s[mt][nt][1] = __expf(s[mt][nt][1] - mn0);
                s[mt][nt][2] = __expf(s[mt][nt][2] - mn1);
                s[mt][nt][3] = __expf(s[mt][nt][3] - mn1);
                sum0 += s[mt][nt][0] + s[mt][nt][1];
                sum1 += s[mt][nt][2] + s[mt][nt][3];
            }
            sum0 += __shfl_xor_sync(0xffffffffu, sum0, 1);
            sum0 += __shfl_xor_sync(0xffffffffu, sum0, 2);
            sum1 += __shfl_xor_sync(0xffffffffu, sum1, 1);
            sum1 += __shfl_xor_sync(0xffffffffu, sum1, 2);
            l_[mt][0] = l_[mt][0] * a0 + sum0;
            l_[mt][1] = l_[mt][1] * a1 + sum1;
            m_[mt][0] = mn0;
            m_[mt][1] = mn1;
#pragma unroll
            for (int dt = 0; dt < 4; dt++) {
                o_[mt][dt][0] *= a0; o_[mt][dt][1] *= a0;
                o_[mt][dt][2] *= a1; o_[mt][dt][3] *= a1;
            }
        }

        // pack P into A-fragments (C-frag per-lane layout == A-frag per-lane layout)
        uint32_t pa[2][4][4];
#pragma unroll
        for (int mt = 0; mt < 2; mt++) {
#pragma unroll
            for (int kc = 0; kc < 4; kc++) {
                pa[mt][kc][0] = pack_bf16x2(s[mt][2 * kc][0],     s[mt][2 * kc][1]);
                pa[mt][kc][1] = pack_bf16x2(s[mt][2 * kc][2],     s[mt][2 * kc][3]);
                pa[mt][kc][2] = pack_bf16x2(s[mt][2 * kc + 1][0], s[mt][2 * kc + 1][1]);
                pa[mt][kc][3] = pack_bf16x2(s[mt][2 * kc + 1][2], s[mt][2 * kc + 1][3]);
            }
        }

        // O += P V  (B-frags from Vt, plain ldmatrix)
#pragma unroll
        for (int dt = 0; dt < 4; dt++) {
            uint32_t vb[4];
            uint32_t vaddr = (uint32_t)__cvta_generic_to_shared(
                &Vts[(dt * 8 + (lane & 7)) * 72 + (lane >> 3) * 8]);
            ldsm_x4(vb, vaddr);                 // tokens 0..31
#pragma unroll
            for (int mt = 0; mt < 2; mt++) {
                mma16816(o_[mt][dt], pa[mt][0], vb[0], vb[1]);
                mma16816(o_[mt][dt], pa[mt][1], vb[2], vb[3]);
            }
            ldsm_x4(vb, vaddr + 64);            // tokens 32..63 (+32 elems = +64 bytes)
#pragma unroll
            for (int mt = 0; mt < 2; mt++) {
                mma16816(o_[mt][dt], pa[mt][2], vb[0], vb[1]);
                mma16816(o_[mt][dt], pa[mt][3], vb[2], vb[3]);
            }
        }
    }

    // normalize + write [b][n][c] fp32
#pragma unroll
    for (int mt = 0; mt < 2; mt++) {
        float inv0 = 1.0f / l_[mt][0];
        float inv1 = 1.0f / l_[mt][1];
        int r0 = n0 + mbase + mt * 16 + (lane >> 2);
#pragma unroll
        for (int dt = 0; dt < 4; dt++) {
            int col = h * 32 + dt * 8 + 2 * (lane & 3);
            float2 lo = make_float2(o_[mt][dt][0] * inv0, o_[mt][dt][1] * inv0);
            float2 hi = make_float2(o_[mt][dt][2] * inv1, o_[mt][dt][3] * inv1);
            *(float2*)&g_ao[(size_t)(b * NTOK + r0) * CH + col]     = lo;
            *(float2*)&g_ao[(size_t)(b * NTOK + r0 + 8) * CH + col] = hi;
        }
    }
}

// ---------------- kernel 4: proj GEMM + bias + residual + token2patch ----------------
__global__ void __launch_bounds__(128) proj_kernel(const float* __restrict__ x,
                                                   const float* __restrict__ w,
                                                   const float* __restrict__ bias,
                                                   float* __restrict__ out) {
    const int b  = blockIdx.z;
    const int m0 = blockIdx.x * 64;
    const int o0 = blockIdx.y * 64;
    const int tid = threadIdx.x;
    const int tx = tid & 15;
    const int ty = tid >> 4;

    __shared__ float As[16 * 68];
    __shared__ float Bs[16 * 68];

    float acc[4][8];
#pragma unroll
    for (int i = 0; i < 4; i++) {
#pragma unroll
        for (int j = 0; j < 8; j++) { acc[i][j] = 0.f; }
    }

    const float* aBase = g_ao + b * NTOK * CH;

    for (int kt = 0; kt < CH; kt += 16) {
#pragma unroll
        for (int i = 0; i < 2; i++) {
            int t4 = tid * 2 + i;
            int m  = t4 >> 2;
            int kq = (t4 & 3) * 4;
            float4 v = *(const float4*)&aBase[(m0 + m) * CH + kt + kq];
            As[(kq + 0) * 68 + m] = v.x;
            As[(kq + 1) * 68 + m] = v.y;
            As[(kq + 2) * 68 + m] = v.z;
            As[(kq + 3) * 68 + m] = v.w;
        }
#pragma unroll
        for (int i = 0; i < 2; i++) {
            int t4 = tid * 2 + i;
            int o  = t4 >> 2;
            int kq = (t4 & 3) * 4;
            float4 v = *(const float4*)&w[(o0 + o) * CH + kt + kq];
            Bs[(kq + 0) * 68 + o] = v.x;
            Bs[(kq + 1) * 68 + o] = v.y;
            Bs[(kq + 2) * 68 + o] = v.z;
            Bs[(kq + 3) * 68 + o] = v.w;
        }
        __syncthreads();
#pragma unroll
        for (int k = 0; k < 16; k++) {
            float4 a  = *(float4*)&As[k * 68 + tx * 4];
            float4 b0 = *(float4*)&Bs[k * 68 + ty * 8];
            float4 b1 = *(float4*)&Bs[k * 68 + ty * 8 + 4];
            float av[4] = {a.x, a.y, a.z, a.w};
            float bv[8] = {b0.x, b0.y, b0.z, b0.w, b1.x, b1.y, b1.z, b1.w};
#pragma unroll
            for (int i = 0; i < 4; i++) {
#pragma unroll
                for (int j = 0; j < 8; j++) { acc[i][j] += av[i] * bv[j]; }
            }
        }
        __syncthreads();
    }

#pragma unroll
    for (int j = 0; j < 8; j++) {
        int o = o0 + ty * 8 + j;
        float bp = __ldg(&bias[o]);
        int base = b * CH * NTOK + o * NTOK + m0 + tx * 4;
        float4 xv = *(const float4*)&x[base];
        float4 r;
        r.x = acc[0][j] + xv.x + bp;
        r.y = acc[1][j] + xv.y + bp;
        r.z = acc[2][j] + xv.z + bp;
        r.w = acc[3][j] + xv.w + bp;
        *(float4*)&out[base] = r;
    }
}

// ---------------- launch ----------------
extern "C" void kernel_launch(void* const* d_in, const int* in_sizes, int n_in,
                              void* d_out, int out_size) {
    const float* x      = (const float*)d_in[0];
    const float* gamma  = (const float*)d_in[1];
    const float* beta   = (const float*)d_in[2];
    const float* w_qkv  = (const float*)d_in[3];
    const float* w_proj = (const float*)d_in[4];
    const float* b_proj = (const float*)d_in[5];
    float* out = (float*)d_out;

    ln_kernel<<<dim3(NTOK / 256, BATCH), 256>>>(x, gamma, beta);
    qkv_gemm_kernel<<<dim3(NTOK / 64, 12, BATCH), 128>>>(w_qkv);
    flash_mma_kernel<<<dim3(NTOK / 128, NHEAD, BATCH), 128>>>();
    proj_kernel<<<dim3(NTOK / 64, CH / 64, BATCH), 128>>>(x, w_proj, b_proj, out);
}

// round 4
// speedup vs baseline: 5.0346x; 1.4571x over previous
#include <cuda_runtime.h>
#include <cuda_bf16.h>
#include <cstdint>

#define BATCH 2
#define CH 256
#define NTOK 4096
#define NHEAD 8
#define HDIM 32
#define SCALE 0.17677669529663687f   // 1/sqrt(32)

// ---------------- scratch (no allocations allowed) ----------------
__device__ __nv_bfloat16 g_tn[BATCH * CH * NTOK];               // layernorm out, [b][c][n] bf16
__device__ __nv_bfloat16 g_q [BATCH * NHEAD * NTOK * HDIM];     // [b][h][n][d], pre-scaled
__device__ __nv_bfloat16 g_k [BATCH * NHEAD * NTOK * HDIM];     // [b][h][n][d]
__device__ __nv_bfloat16 g_v [BATCH * NHEAD * NTOK * HDIM];     // [b][h][n][d]
__device__ __nv_bfloat16 g_ao[BATCH * NTOK * CH];               // attn out, [b][n][c] bf16

// ---------------- mma helpers ----------------
__device__ __forceinline__ void ldsm_x4(uint32_t* r, uint32_t saddr) {
    asm volatile("ldmatrix.sync.aligned.m8n8.x4.shared.b16 {%0,%1,%2,%3}, [%4];"
                 : "=r"(r[0]), "=r"(r[1]), "=r"(r[2]), "=r"(r[3]) : "r"(saddr));
}

__device__ __forceinline__ void ldsm_x4_trans(uint32_t* r, uint32_t saddr) {
    asm volatile("ldmatrix.sync.aligned.m8n8.x4.trans.shared.b16 {%0,%1,%2,%3}, [%4];"
                 : "=r"(r[0]), "=r"(r[1]), "=r"(r[2]), "=r"(r[3]) : "r"(saddr));
}

__device__ __forceinline__ void mma16816(float* c, const uint32_t* a, uint32_t b0, uint32_t b1) {
    asm volatile("mma.sync.aligned.m16n8k16.row.col.f32.bf16.bf16.f32 "
                 "{%0,%1,%2,%3}, {%4,%5,%6,%7}, {%8,%9}, {%0,%1,%2,%3};"
                 : "+f"(c[0]), "+f"(c[1]), "+f"(c[2]), "+f"(c[3])
                 : "r"(a[0]), "r"(a[1]), "r"(a[2]), "r"(a[3]), "r"(b0), "r"(b1));
}

__device__ __forceinline__ uint32_t pack_bf16x2(float lo, float hi) {
    uint32_t r;
    asm("cvt.rn.bf16x2.f32 %0, %1, %2;" : "=r"(r) : "f"(hi), "f"(lo));
    return r;
}

// ---------------- kernel 1: LayerNorm (channel dim), bf16 output ----------------
__global__ void ln_kernel(const float* __restrict__ x,
                          const float* __restrict__ gamma,
                          const float* __restrict__ beta) {
    int n = blockIdx.x * blockDim.x + threadIdx.x;
    int b = blockIdx.y;
    const float* xb = x + b * CH * NTOK + n;
    float s = 0.f, ss = 0.f;
#pragma unroll 8
    for (int c = 0; c < CH; c++) {
        float v = xb[c * NTOK];
        s += v; ss += v * v;
    }
    float mu  = s * (1.0f / CH);
    float var = ss * (1.0f / CH) - mu * mu;
    float r   = rsqrtf(var + 1e-5f);
    __nv_bfloat16* tb = g_tn + b * CH * NTOK + n;
#pragma unroll 8
    for (int c = 0; c < CH; c++) {
        float v = xb[c * NTOK];
        tb[c * NTOK] = __float2bfloat16_rn((v - mu) * r * __ldg(&gamma[c]) + __ldg(&beta[c]));
    }
}

// ---------------- kernel 2: QKV GEMM, bf16 mma ----------------
// C[m][o] = sum_k tn[k][m] * w[o][k].  M tile 128, N tile 64, KC 32 (8 chunks).
// A from k-major g_tn via ldmatrix.trans (pitch 136); B like flash-K (pitch 40).
__global__ void __launch_bounds__(128) qkv_mma_kernel(const float* __restrict__ w) {
    const int b  = blockIdx.z;
    const int m0 = blockIdx.x * 128;
    const int o0 = blockIdx.y * 64;
    const int tid  = threadIdx.x;
    const int warp = tid >> 5;
    const int lane = tid & 31;

    __shared__ __nv_bfloat16 As[32 * 136];   // [k][m]
    __shared__ __nv_bfloat16 Bs[64 * 40];    // [o][k]

    float acc[2][8][4];
#pragma unroll
    for (int mt = 0; mt < 2; mt++) {
#pragma unroll
        for (int nt = 0; nt < 8; nt++) {
#pragma unroll
            for (int c = 0; c < 4; c++) { acc[mt][nt][c] = 0.f; }
        }
    }

    const __nv_bfloat16* aBase = g_tn + (size_t)b * CH * NTOK;

    for (int kt = 0; kt < CH; kt += 32) {
        __syncthreads();
        // A tile: 32k x 128m bf16, gmem n-contiguous -> uint4
#pragma unroll
        for (int ii = 0; ii < 4; ii++) {
            int idx = tid + 128 * ii;            // 0..511
            int k   = idx >> 4;
            int mc  = (idx & 15) * 8;
            *(uint4*)&As[k * 136 + mc] = *(const uint4*)&aBase[(size_t)(kt + k) * NTOK + m0 + mc];
        }
        // B tile: 64o x 32k, fp32 -> bf16 convert
#pragma unroll
        for (int ii = 0; ii < 4; ii++) {
            int idx = tid + 128 * ii;            // 0..511
            int o   = idx >> 3;
            int kk  = (idx & 7) * 4;
            float4 v = *(const float4*)&w[(size_t)(o0 + o) * CH + kt + kk];
            __nv_bfloat16 tmp[4];
            tmp[0] = __float2bfloat16_rn(v.x);
            tmp[1] = __float2bfloat16_rn(v.y);
            tmp[2] = __float2bfloat16_rn(v.z);
            tmp[3] = __float2bfloat16_rn(v.w);
            *(uint2*)&Bs[o * 40 + kk] = *(uint2*)tmp;
        }
        __syncthreads();

        // B frags: one x4 per nt covers k0..31 (2 k-steps)
        uint32_t kb[8][4];
#pragma unroll
        for (int nt = 0; nt < 8; nt++) {
            uint32_t baddr = (uint32_t)__cvta_generic_to_shared(
                &Bs[(nt * 8 + (lane & 7)) * 40 + (lane >> 3) * 8]);
            ldsm_x4(kb[nt], baddr);
        }
        // A frags: per (mt, ks) one x4.trans
#pragma unroll
        for (int ks = 0; ks < 2; ks++) {
            uint32_t af[2][4];
#pragma unroll
            for (int mt = 0; mt < 2; mt++) {
                int mrow0 = warp * 32 + mt * 16;
                uint32_t aaddr = (uint32_t)__cvta_generic_to_shared(
                    &As[(ks * 16 + (lane & 7) + ((lane & 16) >> 1)) * 136 + mrow0 + (lane & 8)]);
                ldsm_x4_trans(af[mt], aaddr);
            }
#pragma unroll
            for (int mt = 0; mt < 2; mt++) {
#pragma unroll
                for (int nt = 0; nt < 8; nt++) {
                    mma16816(acc[mt][nt], af[mt], kb[nt][2 * ks], kb[nt][2 * ks + 1]);
                }
            }
        }
    }

    // epilogue: row = token, col = o -> q/k/v [b][h][n][d], 4B bf16x2 stores
    const int which = o0 >> 8;                   // 0:q 1:k 2:v
    const float sc = (which == 0) ? SCALE : 1.0f;
    __nv_bfloat16* outp = (which == 0) ? g_q : (which == 1) ? g_k : g_v;
#pragma unroll
    for (int mt = 0; mt < 2; mt++) {
#pragma unroll
        for (int nt = 0; nt < 8; nt++) {
            int o  = o0 + nt * 8 + 2 * (lane & 3);
            int h  = (o >> 5) & 7;
            int dd = o & 31;
            int n_lo = m0 + warp * 32 + mt * 16 + (lane >> 2);
            uint32_t lo = pack_bf16x2(acc[mt][nt][0] * sc, acc[mt][nt][1] * sc);
            uint32_t hi = pack_bf16x2(acc[mt][nt][2] * sc, acc[mt][nt][3] * sc);
            *(uint32_t*)&outp[((size_t)(b * NHEAD + h) * NTOK + n_lo) * HDIM + dd]     = lo;
            *(uint32_t*)&outp[((size_t)(b * NHEAD + h) * NTOK + n_lo + 8) * HDIM + dd] = hi;
        }
    }
}

// ---------------- kernel 3: flash attention, bf16 mma.sync ----------------
__global__ void __launch_bounds__(128) flash_mma_kernel() {
    const int b  = blockIdx.z;
    const int h  = blockIdx.y;
    const int n0 = blockIdx.x * 128;
    const int tid  = threadIdx.x;
    const int warp = tid >> 5;
    const int lane = tid & 31;

    __shared__ __nv_bfloat16 Qs[128 * 40];
    __shared__ __nv_bfloat16 Ks[64 * 40];
    __shared__ __nv_bfloat16 Vs[64 * 40];

    const __nv_bfloat16* qsrc = g_q + ((size_t)(b * NHEAD + h) * NTOK + n0) * HDIM;
    const __nv_bfloat16* ksrc = g_k + (size_t)(b * NHEAD + h) * NTOK * HDIM;
    const __nv_bfloat16* vsrc = g_v + (size_t)(b * NHEAD + h) * NTOK * HDIM;

#pragma unroll
    for (int ii = 0; ii < 4; ii++) {
        int idx = tid + 128 * ii;
        int row = idx >> 2;
        int cc  = idx & 3;
        *(uint4*)&Qs[row * 40 + cc * 8] = *(const uint4*)&qsrc[row * 32 + cc * 8];
    }
    __syncthreads();

    uint32_t aq[2][2][4];
    const int mbase = warp * 32;
#pragma unroll
    for (int mt = 0; mt < 2; mt++) {
        uint32_t base = (uint32_t)__cvta_generic_to_shared(
            &Qs[(mbase + mt * 16 + (lane & 15)) * 40 + (lane >> 4) * 8]);
        ldsm_x4(aq[mt][0], base);
        ldsm_x4(aq[mt][1], base + 32);
    }

    float m_[2][2], l_[2][2], o_[2][4][4];
#pragma unroll
    for (int mt = 0; mt < 2; mt++) {
        m_[mt][0] = -1e30f; m_[mt][1] = -1e30f;
        l_[mt][0] = 0.f;    l_[mt][1] = 0.f;
#pragma unroll
        for (int dt = 0; dt < 4; dt++) {
#pragma unroll
            for (int c = 0; c < 4; c++) { o_[mt][dt][c] = 0.f; }
        }
    }

    for (int j0 = 0; j0 < NTOK; j0 += 64) {
        __syncthreads();
#pragma unroll
        for (int ii = 0; ii < 2; ii++) {
            int idx = tid + 128 * ii;
            int row = idx >> 2;
            int cc  = idx & 3;
            *(uint4*)&Ks[row * 40 + cc * 8] = *(const uint4*)&ksrc[(size_t)(j0 + row) * 32 + cc * 8];
            *(uint4*)&Vs[row * 40 + cc * 8] = *(const uint4*)&vsrc[(size_t)(j0 + row) * 32 + cc * 8];
        }
        __syncthreads();

        // S = Q K^T
        float s[2][8][4];
#pragma unroll
        for (int mt = 0; mt < 2; mt++) {
#pragma unroll
            for (int nt = 0; nt < 8; nt++) {
#pragma unroll
                for (int c = 0; c < 4; c++) { s[mt][nt][c] = 0.f; }
            }
        }
#pragma unroll
        for (int nt = 0; nt < 8; nt++) {
            uint32_t kbf[4];
            uint32_t kaddr = (uint32_t)__cvta_generic_to_shared(
                &Ks[(nt * 8 + (lane & 7)) * 40 + (lane >> 3) * 8]);
            ldsm_x4(kbf, kaddr);
#pragma unroll
            for (int mt = 0; mt < 2; mt++) {
                mma16816(s[mt][nt], aq[mt][0], kbf[0], kbf[1]);
                mma16816(s[mt][nt], aq[mt][1], kbf[2], kbf[3]);
            }
        }

        // online softmax
#pragma unroll
        for (int mt = 0; mt < 2; mt++) {
            float mx0 = -1e30f, mx1 = -1e30f;
#pragma unroll
            for (int nt = 0; nt < 8; nt++) {
                mx0 = fmaxf(mx0, fmaxf(s[mt][nt][0], s[mt][nt][1]));
                mx1 = fmaxf(mx1, fmaxf(s[mt][nt][2], s[mt][nt][3]));
            }
            mx0 = fmaxf(mx0, __shfl_xor_sync(0xffffffffu, mx0, 1));
            mx0 = fmaxf(mx0, __shfl_xor_sync(0xffffffffu, mx0, 2));
            mx1 = fmaxf(mx1, __shfl_xor_sync(0xffffffffu, mx1, 1));
            mx1 = fmaxf(mx1, __shfl_xor_sync(0xffffffffu, mx1, 2));
            float mn0 = fmaxf(m_[mt][0], mx0);
            float mn1 = fmaxf(m_[mt][1], mx1);
            float a0 = __expf(m_[mt][0] - mn0);
            float a1 = __expf(m_[mt][1] - mn1);
            float sum0 = 0.f, sum1 = 0.f;
#pragma unroll
            for (int nt = 0; nt < 8; nt++) {
                s[mt][nt][0] = __expf(s[mt][nt][0] - mn0);
                s[mt][nt][1] = __expf(s[mt][nt][1] - mn0);
                s[mt][nt][2] = __expf(s[mt][nt][2] - mn1);
                s[mt][nt][3] = __expf(s[mt][nt][3] - mn1);
                sum0 += s[mt][nt][0] + s[mt][nt][1];
                sum1 += s[mt][nt][2] + s[mt][nt][3];
            }
            sum0 += __shfl_xor_sync(0xffffffffu, sum0, 1);
            sum0 += __shfl_xor_sync(0xffffffffu, sum0, 2);
            sum1 += __shfl_xor_sync(0xffffffffu, sum1, 1);
            sum1 += __shfl_xor_sync(0xffffffffu, sum1, 2);
            l_[mt][0] = l_[mt][0] * a0 + sum0;
            l_[mt][1] = l_[mt][1] * a1 + sum1;
            m_[mt][0] = mn0;
            m_[mt][1] = mn1;
#pragma unroll
            for (int dt = 0; dt < 4; dt++) {
                o_[mt][dt][0] *= a0; o_[mt][dt][1] *= a0;
                o_[mt][dt][2] *= a1; o_[mt][dt][3] *= a1;
            }
        }

        // pack P into A-frags
        uint32_t pa[2][4][4];
#pragma unroll
        for (int mt = 0; mt < 2; mt++) {
#pragma unroll
            for (int kc = 0; kc < 4; kc++) {
                pa[mt][kc][0] = pack_bf16x2(s[mt][2 * kc][0],     s[mt][2 * kc][1]);
                pa[mt][kc][1] = pack_bf16x2(s[mt][2 * kc][2],     s[mt][2 * kc][3]);
                pa[mt][kc][2] = pack_bf16x2(s[mt][2 * kc + 1][0], s[mt][2 * kc + 1][1]);
                pa[mt][kc][3] = pack_bf16x2(s[mt][2 * kc + 1][2], s[mt][2 * kc + 1][3]);
            }
        }

        // O += P V : B-frags via ldmatrix.trans on [token][d] V tiles
#pragma unroll
        for (int kc = 0; kc < 4; kc++) {
#pragma unroll
            for (int db = 0; db < 2; db++) {
                uint32_t vb[4];
                uint32_t vaddr = (uint32_t)__cvta_generic_to_shared(
                    &Vs[(kc * 16 + (lane & 15)) * 40 + db * 16 + (lane >> 4) * 8]);
                ldsm_x4_trans(vb, vaddr);
#pragma unroll
                for (int mt = 0; mt < 2; mt++) {
                    mma16816(o_[mt][db * 2],     pa[mt][kc], vb[0], vb[1]);
                    mma16816(o_[mt][db * 2 + 1], pa[mt][kc], vb[2], vb[3]);
                }
            }
        }
    }

    // normalize + write [b][n][c] bf16
#pragma unroll
    for (int mt = 0; mt < 2; mt++) {
        float inv0 = 1.0f / l_[mt][0];
        float inv1 = 1.0f / l_[mt][1];
        int r0 = n0 + mbase + mt * 16 + (lane >> 2);
#pragma unroll
        for (int dt = 0; dt < 4; dt++) {
            int col = h * 32 + dt * 8 + 2 * (lane & 3);
            uint32_t lo = pack_bf16x2(o_[mt][dt][0] * inv0, o_[mt][dt][1] * inv0);
            uint32_t hi = pack_bf16x2(o_[mt][dt][2] * inv1, o_[mt][dt][3] * inv1);
            *(uint32_t*)&g_ao[(size_t)(b * NTOK + r0) * CH + col]     = lo;
            *(uint32_t*)&g_ao[(size_t)(b * NTOK + r0 + 8) * CH + col] = hi;
        }
    }
}

// ---------------- kernel 4: proj GEMM, bf16 mma + bias + residual ----------------
// C[n][o] = sum_k ao[n][k] * w[o][k];  out[b][o][n] = C + x + bias
__global__ void __launch_bounds__(128) proj_mma_kernel(const float* __restrict__ x,
                                                       const float* __restrict__ w,
                                                       const float* __restrict__ bias,
                                                       float* __restrict__ out) {
    const int b  = blockIdx.z;
    const int m0 = blockIdx.x * 128;   // tokens
    const int o0 = blockIdx.y * 64;    // output channels
    const int tid  = threadIdx.x;
    const int warp = tid >> 5;
    const int lane = tid & 31;

    __shared__ __nv_bfloat16 As[128 * 40];   // [m][k]
    __shared__ __nv_bfloat16 Bs[64 * 40];    // [o][k]

    float acc[2][8][4];
#pragma unroll
    for (int mt = 0; mt < 2; mt++) {
#pragma unroll
        for (int nt = 0; nt < 8; nt++) {
#pragma unroll
            for (int c = 0; c < 4; c++) { acc[mt][nt][c] = 0.f; }
        }
    }

    const __nv_bfloat16* aBase = g_ao + (size_t)b * NTOK * CH;

    for (int kt = 0; kt < CH; kt += 32) {
        __syncthreads();
#pragma unroll
        for (int ii = 0; ii < 4; ii++) {
            int idx = tid + 128 * ii;            // 0..511
            int m   = idx >> 2;
            int kk  = (idx & 3) * 8;
            *(uint4*)&As[m * 40 + kk] = *(const uint4*)&aBase[(size_t)(m0 + m) * CH + kt + kk];
        }
#pragma unroll
        for (int ii = 0; ii < 4; ii++) {
            int idx = tid + 128 * ii;
            int o   = idx >> 3;
            int kk  = (idx & 7) * 4;
            float4 v = *(const float4*)&w[(size_t)(o0 + o) * CH + kt + kk];
            __nv_bfloat16 tmp[4];
            tmp[0] = __float2bfloat16_rn(v.x);
            tmp[1] = __float2bfloat16_rn(v.y);
            tmp[2] = __float2bfloat16_rn(v.z);
            tmp[3] = __float2bfloat16_rn(v.w);
            *(uint2*)&Bs[o * 40 + kk] = *(uint2*)tmp;
        }
        __syncthreads();

        uint32_t kb[8][4];
#pragma unroll
        for (int nt = 0; nt < 8; nt++) {
            uint32_t baddr = (uint32_t)__cvta_generic_to_shared(
                &Bs[(nt * 8 + (lane & 7)) * 40 + (lane >> 3) * 8]);
            ldsm_x4(kb[nt], baddr);
        }
#pragma unroll
        for (int mt = 0; mt < 2; mt++) {
            int mrow0 = warp * 32 + mt * 16;
            uint32_t abase = (uint32_t)__cvta_generic_to_shared(
                &As[(mrow0 + (lane & 15)) * 40 + (lane >> 4) * 8]);
            uint32_t af0[4], af1[4];
            ldsm_x4(af0, abase);         // k 0..15
            ldsm_x4(af1, abase + 32);    // k 16..31
#pragma unroll
            for (int nt = 0; nt < 8; nt++) {
                mma16816(acc[mt][nt], af0, kb[nt][0], kb[nt][1]);
                mma16816(acc[mt][nt], af1, kb[nt][2], kb[nt][3]);
            }
        }
    }

    // epilogue: out[b][o][n] = acc + x + bias (rows n, cols o -> strided 4B stores)
#pragma unroll
    for (int mt = 0; mt < 2; mt++) {
#pragma unroll
        for (int nt = 0; nt < 8; nt++) {
            int o  = o0 + nt * 8 + 2 * (lane & 3);
            int n_lo = m0 + warp * 32 + mt * 16 + (lane >> 2);
            float bp0 = __ldg(&bias[o]);
            float bp1 = __ldg(&bias[o + 1]);
            size_t i00 = (size_t)b * CH * NTOK + (size_t)o * NTOK + n_lo;
            size_t i01 = i00 + NTOK;
            out[i00]     = acc[mt][nt][0] + x[i00]     + bp0;
            out[i01]     = acc[mt][nt][1] + x[i01]     + bp1;
            out[i00 + 8] = acc[mt][nt][2] + x[i00 + 8] + bp0;
            out[i01 + 8] = acc[mt][nt][3] + x[i01 + 8] + bp1;
        }
    }
}

// ---------------- launch ----------------
extern "C" void kernel_launch(void* const* d_in, const int* in_sizes, int n_in,
                              void* d_out, int out_size) {
    const float* x      = (const float*)d_in[0];
    const float* gamma  = (const float*)d_in[1];
    const float* beta   = (const float*)d_in[2];
    const float* w_qkv  = (const float*)d_in[3];
    const float* w_proj = (const float*)d_in[4];
    const float* b_proj = (const float*)d_in[5];
    float* out = (float*)d_out;

    ln_kernel<<<dim3(NTOK / 256, BATCH), 256>>>(x, gamma, beta);
    qkv_mma_kernel<<<dim3(NTOK / 128, 12, BATCH), 128>>>(w_qkv);
    flash_mma_kernel<<<dim3(NTOK / 128, NHEAD, BATCH), 128>>>();
    proj_mma_kernel<<<dim3(NTOK / 128, CH / 64, BATCH), 128>>>(x, w_proj, b_proj, out);
}

// round 5
// speedup vs baseline: 5.8503x; 1.1620x over previous
#include <cuda_runtime.h>
#include <cuda_bf16.h>
#include <cstdint>

#define BATCH 2
#define CH 256
#define NTOK 4096
#define NHEAD 8
#define HDIM 32
#define SCALE 0.17677669529663687f           // 1/sqrt(32)
#define SCALE_LOG2E 0.2550316805267167f      // SCALE * log2(e)  (flash logits in log2 domain)

// ---------------- scratch (no allocations allowed) ----------------
__device__ __nv_bfloat16 g_tn[BATCH * CH * NTOK];               // layernorm out, [b][c][n] bf16
__device__ __nv_bfloat16 g_q [BATCH * NHEAD * NTOK * HDIM];     // [b][h][n][d], pre-scaled by SCALE_LOG2E
__device__ __nv_bfloat16 g_k [BATCH * NHEAD * NTOK * HDIM];     // [b][h][n][d]
__device__ __nv_bfloat16 g_v [BATCH * NHEAD * NTOK * HDIM];     // [b][h][n][d]
__device__ __nv_bfloat16 g_ao[BATCH * NTOK * CH];               // attn out, [b][n][c] bf16

// ---------------- helpers ----------------
__device__ __forceinline__ void ldsm_x4(uint32_t* r, uint32_t saddr) {
    asm volatile("ldmatrix.sync.aligned.m8n8.x4.shared.b16 {%0,%1,%2,%3}, [%4];"
                 : "=r"(r[0]), "=r"(r[1]), "=r"(r[2]), "=r"(r[3]) : "r"(saddr));
}
__device__ __forceinline__ void ldsm_x4_trans(uint32_t* r, uint32_t saddr) {
    asm volatile("ldmatrix.sync.aligned.m8n8.x4.trans.shared.b16 {%0,%1,%2,%3}, [%4];"
                 : "=r"(r[0]), "=r"(r[1]), "=r"(r[2]), "=r"(r[3]) : "r"(saddr));
}
__device__ __forceinline__ void mma16816(float* c, const uint32_t* a, uint32_t b0, uint32_t b1) {
    asm volatile("mma.sync.aligned.m16n8k16.row.col.f32.bf16.bf16.f32 "
                 "{%0,%1,%2,%3}, {%4,%5,%6,%7}, {%8,%9}, {%0,%1,%2,%3};"
                 : "+f"(c[0]), "+f"(c[1]), "+f"(c[2]), "+f"(c[3])
                 : "r"(a[0]), "r"(a[1]), "r"(a[2]), "r"(a[3]), "r"(b0), "r"(b1));
}
__device__ __forceinline__ uint32_t pack_bf16x2(float lo, float hi) {
    uint32_t r;
    asm("cvt.rn.bf16x2.f32 %0, %1, %2;" : "=r"(r) : "f"(hi), "f"(lo));
    return r;
}
__device__ __forceinline__ uint32_t ex2_bf16x2(uint32_t u) {
    uint32_t r;
    asm("ex2.approx.ftz.bf16x2 %0, %1;" : "=r"(r) : "r"(u));
    return r;
}
__device__ __forceinline__ float ex2f(float x) {
    float r;
    asm("ex2.approx.f32 %0, %1;" : "=f"(r) : "f"(x));
    return r;
}
__device__ __forceinline__ void cp_async16(uint32_t saddr, const void* gptr) {
    asm volatile("cp.async.cg.shared.global [%0], [%1], 16;" :: "r"(saddr), "l"(gptr));
}
#define CP_COMMIT() asm volatile("cp.async.commit_group;")
#define CP_WAIT1()  asm volatile("cp.async.wait_group 1;")

// ---------------- kernel 1: LayerNorm (channel dim), bf16 output ----------------
__global__ void ln_kernel(const float* __restrict__ x,
                          const float* __restrict__ gamma,
                          const float* __restrict__ beta) {
    int n = blockIdx.x * blockDim.x + threadIdx.x;
    int b = blockIdx.y;
    const float* xb = x + b * CH * NTOK + n;
    float s = 0.f, ss = 0.f;
#pragma unroll 8
    for (int c = 0; c < CH; c++) {
        float v = xb[c * NTOK];
        s += v; ss += v * v;
    }
    float mu  = s * (1.0f / CH);
    float var = ss * (1.0f / CH) - mu * mu;
    float r   = rsqrtf(var + 1e-5f);
    __nv_bfloat16* tb = g_tn + b * CH * NTOK + n;
#pragma unroll 8
    for (int c = 0; c < CH; c++) {
        float v = xb[c * NTOK];
        tb[c * NTOK] = __float2bfloat16_rn((v - mu) * r * __ldg(&gamma[c]) + __ldg(&beta[c]));
    }
}

// ---------------- kernel 2: QKV GEMM, bf16 mma ----------------
__global__ void __launch_bounds__(128) qkv_mma_kernel(const float* __restrict__ w) {
    const int b  = blockIdx.z;
    const int m0 = blockIdx.x * 128;
    const int o0 = blockIdx.y * 64;
    const int tid  = threadIdx.x;
    const int warp = tid >> 5;
    const int lane = tid & 31;

    __shared__ __nv_bfloat16 As[32 * 136];   // [k][m]
    __shared__ __nv_bfloat16 Bs[64 * 40];    // [o][k]

    float acc[2][8][4];
#pragma unroll
    for (int mt = 0; mt < 2; mt++) {
#pragma unroll
        for (int nt = 0; nt < 8; nt++) {
#pragma unroll
            for (int c = 0; c < 4; c++) { acc[mt][nt][c] = 0.f; }
        }
    }

    const __nv_bfloat16* aBase = g_tn + (size_t)b * CH * NTOK;

    for (int kt = 0; kt < CH; kt += 32) {
        __syncthreads();
#pragma unroll
        for (int ii = 0; ii < 4; ii++) {
            int idx = tid + 128 * ii;
            int k   = idx >> 4;
            int mc  = (idx & 15) * 8;
            *(uint4*)&As[k * 136 + mc] = *(const uint4*)&aBase[(size_t)(kt + k) * NTOK + m0 + mc];
        }
#pragma unroll
        for (int ii = 0; ii < 4; ii++) {
            int idx = tid + 128 * ii;
            int o   = idx >> 3;
            int kk  = (idx & 7) * 4;
            float4 v = *(const float4*)&w[(size_t)(o0 + o) * CH + kt + kk];
            __nv_bfloat16 tmp[4];
            tmp[0] = __float2bfloat16_rn(v.x);
            tmp[1] = __float2bfloat16_rn(v.y);
            tmp[2] = __float2bfloat16_rn(v.z);
            tmp[3] = __float2bfloat16_rn(v.w);
            *(uint2*)&Bs[o * 40 + kk] = *(uint2*)tmp;
        }
        __syncthreads();

        uint32_t kb[8][4];
#pragma unroll
        for (int nt = 0; nt < 8; nt++) {
            uint32_t baddr = (uint32_t)__cvta_generic_to_shared(
                &Bs[(nt * 8 + (lane & 7)) * 40 + (lane >> 3) * 8]);
            ldsm_x4(kb[nt], baddr);
        }
#pragma unroll
        for (int ks = 0; ks < 2; ks++) {
            uint32_t af[2][4];
#pragma unroll
            for (int mt = 0; mt < 2; mt++) {
                int mrow0 = warp * 32 + mt * 16;
                uint32_t aaddr = (uint32_t)__cvta_generic_to_shared(
                    &As[(ks * 16 + (lane & 7) + ((lane & 16) >> 1)) * 136 + mrow0 + (lane & 8)]);
                ldsm_x4_trans(af[mt], aaddr);
            }
#pragma unroll
            for (int mt = 0; mt < 2; mt++) {
#pragma unroll
                for (int nt = 0; nt < 8; nt++) {
                    mma16816(acc[mt][nt], af[mt], kb[nt][2 * ks], kb[nt][2 * ks + 1]);
                }
            }
        }
    }

    const int which = o0 >> 8;                   // 0:q 1:k 2:v
    const float sc = (which == 0) ? SCALE_LOG2E : 1.0f;
    __nv_bfloat16* outp = (which == 0) ? g_q : (which == 1) ? g_k : g_v;
#pragma unroll
    for (int mt = 0; mt < 2; mt++) {
#pragma unroll
        for (int nt = 0; nt < 8; nt++) {
            int o  = o0 + nt * 8 + 2 * (lane & 3);
            int h  = (o >> 5) & 7;
            int dd = o & 31;
            int n_lo = m0 + warp * 32 + mt * 16 + (lane >> 2);
            uint32_t lo = pack_bf16x2(acc[mt][nt][0] * sc, acc[mt][nt][1] * sc);
            uint32_t hi = pack_bf16x2(acc[mt][nt][2] * sc, acc[mt][nt][3] * sc);
            *(uint32_t*)&outp[((size_t)(b * NHEAD + h) * NTOK + n_lo) * HDIM + dd]     = lo;
            *(uint32_t*)&outp[((size_t)(b * NHEAD + h) * NTOK + n_lo + 8) * HDIM + dd] = hi;
        }
    }
}

// ---------------- kernel 3: flash attention, bf16 mma + cp.async pipeline ----------------
// Logits are in log2 domain (log2e folded into Q). P computed with ex2.approx.bf16x2,
// directly forming the PV A-fragments; l summed from the same bf16 values (self-consistent).
__global__ void __launch_bounds__(128) flash_mma_kernel() {
    const int b  = blockIdx.z;
    const int h  = blockIdx.y;
    const int n0 = blockIdx.x * 128;
    const int tid  = threadIdx.x;
    const int warp = tid >> 5;
    const int lane = tid & 31;

    __shared__ __nv_bfloat16 Qs[128 * 40];
    __shared__ __nv_bfloat16 Ks[2][64 * 40];
    __shared__ __nv_bfloat16 Vs[2][64 * 40];

    const __nv_bfloat16* qsrc = g_q + ((size_t)(b * NHEAD + h) * NTOK + n0) * HDIM;
    const __nv_bfloat16* ksrc = g_k + (size_t)(b * NHEAD + h) * NTOK * HDIM;
    const __nv_bfloat16* vsrc = g_v + (size_t)(b * NHEAD + h) * NTOK * HDIM;

    // per-thread K/V load slots: 2 rows each of K and V per stage
    const int lrow = tid >> 2;        // 0..31
    const int lcc  = tid & 3;         // 16B chunk

    // load Q (direct)
#pragma unroll
    for (int ii = 0; ii < 4; ii++) {
        int idx = tid + 128 * ii;
        int row = idx >> 2;
        int cc  = idx & 3;
        *(uint4*)&Qs[row * 40 + cc * 8] = *(const uint4*)&qsrc[row * 32 + cc * 8];
    }

    // prologue: async-load KV stage 0
    {
#pragma unroll
        for (int ii = 0; ii < 2; ii++) {
            int row = lrow + 32 * ii;
            uint32_t kd = (uint32_t)__cvta_generic_to_shared(&Ks[0][row * 40 + lcc * 8]);
            uint32_t vd = (uint32_t)__cvta_generic_to_shared(&Vs[0][row * 40 + lcc * 8]);
            cp_async16(kd, &ksrc[(size_t)row * 32 + lcc * 8]);
            cp_async16(vd, &vsrc[(size_t)row * 32 + lcc * 8]);
        }
        CP_COMMIT();
    }
    __syncthreads();

    // preload Q A-fragments
    uint32_t aq[2][2][4];
    const int mbase = warp * 32;
#pragma unroll
    for (int mt = 0; mt < 2; mt++) {
        uint32_t base = (uint32_t)__cvta_generic_to_shared(
            &Qs[(mbase + mt * 16 + (lane & 15)) * 40 + (lane >> 4) * 8]);
        ldsm_x4(aq[mt][0], base);
        ldsm_x4(aq[mt][1], base + 32);
    }

    float m_[2][2], l_[2][2], o_[2][4][4];
#pragma unroll
    for (int mt = 0; mt < 2; mt++) {
        m_[mt][0] = -1e30f; m_[mt][1] = -1e30f;
        l_[mt][0] = 0.f;    l_[mt][1] = 0.f;
#pragma unroll
        for (int dt = 0; dt < 4; dt++) {
#pragma unroll
            for (int c = 0; c < 4; c++) { o_[mt][dt][c] = 0.f; }
        }
    }

    const int NITER = NTOK / 64;
    for (int it = 0; it < NITER; it++) {
        const int st = it & 1;
        // issue next stage
        if (it + 1 < NITER) {
            int j1 = (it + 1) * 64;
#pragma unroll
            for (int ii = 0; ii < 2; ii++) {
                int row = lrow + 32 * ii;
                uint32_t kd = (uint32_t)__cvta_generic_to_shared(&Ks[st ^ 1][row * 40 + lcc * 8]);
                uint32_t vd = (uint32_t)__cvta_generic_to_shared(&Vs[st ^ 1][row * 40 + lcc * 8]);
                cp_async16(kd, &ksrc[(size_t)(j1 + row) * 32 + lcc * 8]);
                cp_async16(vd, &vsrc[(size_t)(j1 + row) * 32 + lcc * 8]);
            }
        }
        CP_COMMIT();
        CP_WAIT1();         // current stage's group complete
        __syncthreads();

        const __nv_bfloat16* KsS = Ks[st];
        const __nv_bfloat16* VsS = Vs[st];

        // S = Q K^T  (log2-domain logits)
        float s[2][8][4];
#pragma unroll
        for (int mt = 0; mt < 2; mt++) {
#pragma unroll
            for (int nt = 0; nt < 8; nt++) {
#pragma unroll
                for (int c = 0; c < 4; c++) { s[mt][nt][c] = 0.f; }
            }
        }
#pragma unroll
        for (int nt = 0; nt < 8; nt++) {
            uint32_t kbf[4];
            uint32_t kaddr = (uint32_t)__cvta_generic_to_shared(
                &KsS[(nt * 8 + (lane & 7)) * 40 + (lane >> 3) * 8]);
            ldsm_x4(kbf, kaddr);
#pragma unroll
            for (int mt = 0; mt < 2; mt++) {
                mma16816(s[mt][nt], aq[mt][0], kbf[0], kbf[1]);
                mma16816(s[mt][nt], aq[mt][1], kbf[2], kbf[3]);
            }
        }

        // online softmax in log2 domain; P emitted as packed bf16x2 (PV A-frags)
        uint32_t pa[2][4][4];
#pragma unroll
        for (int mt = 0; mt < 2; mt++) {
            float mx0 = -1e30f, mx1 = -1e30f;
#pragma unroll
            for (int nt = 0; nt < 8; nt++) {
                mx0 = fmaxf(mx0, fmaxf(s[mt][nt][0], s[mt][nt][1]));
                mx1 = fmaxf(mx1, fmaxf(s[mt][nt][2], s[mt][nt][3]));
            }
            mx0 = fmaxf(mx0, __shfl_xor_sync(0xffffffffu, mx0, 1));
            mx0 = fmaxf(mx0, __shfl_xor_sync(0xffffffffu, mx0, 2));
            mx1 = fmaxf(mx1, __shfl_xor_sync(0xffffffffu, mx1, 1));
            mx1 = fmaxf(mx1, __shfl_xor_sync(0xffffffffu, mx1, 2));
            float mn0 = fmaxf(m_[mt][0], mx0);
            float mn1 = fmaxf(m_[mt][1], mx1);
            float a0 = ex2f(m_[mt][0] - mn0);
            float a1 = ex2f(m_[mt][1] - mn1);
            float sum0 = 0.f, sum1 = 0.f;
#pragma unroll
            for (int nt = 0; nt < 8; nt++) {
                uint32_t u01 = pack_bf16x2(s[mt][nt][0] - mn0, s[mt][nt][1] - mn0);
                uint32_t u23 = pack_bf16x2(s[mt][nt][2] - mn1, s[mt][nt][3] - mn1);
                uint32_t e01 = ex2_bf16x2(u01);
                uint32_t e23 = ex2_bf16x2(u23);
                pa[mt][nt >> 1][(nt & 1) * 2]     = e01;
                pa[mt][nt >> 1][(nt & 1) * 2 + 1] = e23;
                sum0 += __uint_as_float(e01 << 16) + __uint_as_float(e01 & 0xffff0000u);
                sum1 += __uint_as_float(e23 << 16) + __uint_as_float(e23 & 0xffff0000u);
            }
            sum0 += __shfl_xor_sync(0xffffffffu, sum0, 1);
            sum0 += __shfl_xor_sync(0xffffffffu, sum0, 2);
            sum1 += __shfl_xor_sync(0xffffffffu, sum1, 1);
            sum1 += __shfl_xor_sync(0xffffffffu, sum1, 2);
            l_[mt][0] = l_[mt][0] * a0 + sum0;
            l_[mt][1] = l_[mt][1] * a1 + sum1;
            m_[mt][0] = mn0;
            m_[mt][1] = mn1;
#pragma unroll
            for (int dt = 0; dt < 4; dt++) {
                o_[mt][dt][0] *= a0; o_[mt][dt][1] *= a0;
                o_[mt][dt][2] *= a1; o_[mt][dt][3] *= a1;
            }
        }

        // O += P V : B-frags via ldmatrix.trans on [token][d] V tiles
#pragma unroll
        for (int kc = 0; kc < 4; kc++) {
#pragma unroll
            for (int db = 0; db < 2; db++) {
                uint32_t vb[4];
                uint32_t vaddr = (uint32_t)__cvta_generic_to_shared(
                    &VsS[(kc * 16 + (lane & 15)) * 40 + db * 16 + (lane >> 4) * 8]);
                ldsm_x4_trans(vb, vaddr);
#pragma unroll
                for (int mt = 0; mt < 2; mt++) {
                    mma16816(o_[mt][db * 2],     pa[mt][kc], vb[0], vb[1]);
                    mma16816(o_[mt][db * 2 + 1], pa[mt][kc], vb[2], vb[3]);
                }
            }
        }
        __syncthreads();   // all reads of stage st done -> next iter may overwrite
    }

    // normalize + write [b][n][c] bf16
#pragma unroll
    for (int mt = 0; mt < 2; mt++) {
        float inv0 = 1.0f / l_[mt][0];
        float inv1 = 1.0f / l_[mt][1];
        int r0 = n0 + mbase + mt * 16 + (lane >> 2);
#pragma unroll
        for (int dt = 0; dt < 4; dt++) {
            int col = h * 32 + dt * 8 + 2 * (lane & 3);
            uint32_t lo = pack_bf16x2(o_[mt][dt][0] * inv0, o_[mt][dt][1] * inv0);
            uint32_t hi = pack_bf16x2(o_[mt][dt][2] * inv1, o_[mt][dt][3] * inv1);
            *(uint32_t*)&g_ao[(size_t)(b * NTOK + r0) * CH + col]     = lo;
            *(uint32_t*)&g_ao[(size_t)(b * NTOK + r0 + 8) * CH + col] = hi;
        }
    }
}

// ---------------- kernel 4: proj GEMM, bf16 mma + bias + residual ----------------
__global__ void __launch_bounds__(128) proj_mma_kernel(const float* __restrict__ x,
                                                       const float* __restrict__ w,
                                                       const float* __restrict__ bias,
                                                       float* __restrict__ out) {
    const int b  = blockIdx.z;
    const int m0 = blockIdx.x * 128;
    const int o0 = blockIdx.y * 64;
    const int tid  = threadIdx.x;
    const int warp = tid >> 5;
    const int lane = tid & 31;

    __shared__ __nv_bfloat16 As[128 * 40];
    __shared__ __nv_bfloat16 Bs[64 * 40];

    float acc[2][8][4];
#pragma unroll
    for (int mt = 0; mt < 2; mt++) {
#pragma unroll
        for (int nt = 0; nt < 8; nt++) {
#pragma unroll
            for (int c = 0; c < 4; c++) { acc[mt][nt][c] = 0.f; }
        }
    }

    const __nv_bfloat16* aBase = g_ao + (size_t)b * NTOK * CH;

    for (int kt = 0; kt < CH; kt += 32) {
        __syncthreads();
#pragma unroll
        for (int ii = 0; ii < 4; ii++) {
            int idx = tid + 128 * ii;
            int m   = idx >> 2;
            int kk  = (idx & 3) * 8;
            *(uint4*)&As[m * 40 + kk] = *(const uint4*)&aBase[(size_t)(m0 + m) * CH + kt + kk];
        }
#pragma unroll
        for (int ii = 0; ii < 4; ii++) {
            int idx = tid + 128 * ii;
            int o   = idx >> 3;
            int kk  = (idx & 7) * 4;
            float4 v = *(const float4*)&w[(size_t)(o0 + o) * CH + kt + kk];
            __nv_bfloat16 tmp[4];
            tmp[0] = __float2bfloat16_rn(v.x);
            tmp[1] = __float2bfloat16_rn(v.y);
            tmp[2] = __float2bfloat16_rn(v.z);
            tmp[3] = __float2bfloat16_rn(v.w);
            *(uint2*)&Bs[o * 40 + kk] = *(uint2*)tmp;
        }
        __syncthreads();

        uint32_t kb[8][4];
#pragma unroll
        for (int nt = 0; nt < 8; nt++) {
            uint32_t baddr = (uint32_t)__cvta_generic_to_shared(
                &Bs[(nt * 8 + (lane & 7)) * 40 + (lane >> 3) * 8]);
            ldsm_x4(kb[nt], baddr);
        }
#pragma unroll
        for (int mt = 0; mt < 2; mt++) {
            int mrow0 = warp * 32 + mt * 16;
            uint32_t abase = (uint32_t)__cvta_generic_to_shared(
                &As[(mrow0 + (lane & 15)) * 40 + (lane >> 4) * 8]);
            uint32_t af0[4], af1[4];
            ldsm_x4(af0, abase);
            ldsm_x4(af1, abase + 32);
#pragma unroll
            for (int nt = 0; nt < 8; nt++) {
                mma16816(acc[mt][nt], af0, kb[nt][0], kb[nt][1]);
                mma16816(acc[mt][nt], af1, kb[nt][2], kb[nt][3]);
            }
        }
    }

#pragma unroll
    for (int mt = 0; mt < 2; mt++) {
#pragma unroll
        for (int nt = 0; nt < 8; nt++) {
            int o  = o0 + nt * 8 + 2 * (lane & 3);
            int n_lo = m0 + warp * 32 + mt * 16 + (lane >> 2);
            float bp0 = __ldg(&bias[o]);
            float bp1 = __ldg(&bias[o + 1]);
            size_t i00 = (size_t)b * CH * NTOK + (size_t)o * NTOK + n_lo;
            size_t i01 = i00 + NTOK;
            out[i00]     = acc[mt][nt][0] + x[i00]     + bp0;
            out[i01]     = acc[mt][nt][1] + x[i01]     + bp1;
            out[i00 + 8] = acc[mt][nt][2] + x[i00 + 8] + bp0;
            out[i01 + 8] = acc[mt][nt][3] + x[i01 + 8] + bp1;
        }
    }
}

// ---------------- launch ----------------
extern "C" void kernel_launch(void* const* d_in, const int* in_sizes, int n_in,
                              void* d_out, int out_size) {
    const float* x      = (const float*)d_in[0];
    const float* gamma  = (const float*)d_in[1];
    const float* beta   = (const float*)d_in[2];
    const float* w_qkv  = (const float*)d_in[3];
    const float* w_proj = (const float*)d_in[4];
    const float* b_proj = (const float*)d_in[5];
    float* out = (float*)d_out;

    ln_kernel<<<dim3(NTOK / 256, BATCH), 256>>>(x, gamma, beta);
    qkv_mma_kernel<<<dim3(NTOK / 128, 12, BATCH), 128>>>(w_qkv);
    flash_mma_kernel<<<dim3(NTOK / 128, NHEAD, BATCH), 128>>>();
    proj_mma_kernel<<<dim3(NTOK / 128, CH / 64, BATCH), 128>>>(x, w_proj, b_proj, out);
}